// round 6
// baseline (speedup 1.0000x reference)
#include <cuda_runtime.h>
#include <math.h>

#define RP 32
#define RR 8
#define NB 8
#define NPT 32768
#define PI_F 3.14159265358979323846f

// ---------------- scratch (device globals; no allocation allowed) ----------------
__device__ float g_ft[NB * RR * RP * RP];     // (b, r, theta, phi)
__device__ float g_h1[NB * 32 * RP * RP];     // conv1 out
__device__ float g_h2[NB * 64 * RP * RP];     // conv2 out
__device__ float g_ftmax[NB * 64];
__device__ float g_Bvec[NB * 64];
__device__ float g_wq[RP];
__device__ float g_wc1[8 * 9 * 32];           // conv1 weights, [ic*9+k9][oc]
__device__ float g_wc2[32 * 9 * 64];          // conv2 weights, [ic*9+k9][oc]

// ---------------- f32x2 packed helpers ------------------------------------------
__device__ __forceinline__ unsigned long long ffma2(unsigned long long a,
                                                    unsigned long long b,
                                                    unsigned long long c) {
    unsigned long long d;
    asm("fma.rn.f32x2 %0, %1, %2, %3;" : "=l"(d) : "l"(a), "l"(b), "l"(c));
    return d;
}
__device__ __forceinline__ unsigned long long pack2(float lo, float hi) {
    unsigned long long d;
    asm("mov.b64 %0, {%1, %2};" : "=l"(d) : "f"(lo), "f"(hi));
    return d;
}
__device__ __forceinline__ void unpack2(unsigned long long v, float& lo, float& hi) {
    asm("mov.b64 {%0, %1}, %2;" : "=f"(lo), "=f"(hi) : "l"(v));
}

// ---------------- init: zero grid + quadrature weights --------------------------
__global__ void k_init() {
    int i = blockIdx.x * blockDim.x + threadIdx.x;   // 65536 threads
    g_ft[i] = 0.f;                                   // exactly covers 65536
    if (i < RP) {
        double jj = (double)i;
        double theta = M_PI * (2.0 * jj + 1.0) / 64.0;
        double s = 0.0;
        for (int k = 0; k < 16; k++)
            s += sin((2.0 * jj + 1.0) * (2.0 * k + 1.0) * M_PI / 64.0) / (2.0 * k + 1.0);
        g_wq[i] = (float)((2.0 / 16.0) * sin(theta) * s);
    }
}

// ---------------- weight transpose for coalesced conv fills ---------------------
__global__ void k_wprep(const float* __restrict__ W1, const float* __restrict__ W2) {
    int idx = blockIdx.x * blockDim.x + threadIdx.x;   // 72 * 256 = 18432
    if (idx < 8 * 9 * 32) {
        int ic9 = idx >> 5, oc = idx & 31;
        g_wc1[idx] = W1[oc * 72 + ic9];
    }
    if (idx < 32 * 9 * 64) {
        int ic9 = idx >> 6, oc = idx & 63;
        g_wc2[idx] = W2[oc * 288 + ic9];
    }
}

// ---------------- scatter: gaussian splat of w into (b, r, t, p) grid ------------
__global__ void __launch_bounds__(256) k_scatter(const float* __restrict__ pts,
                          const float* __restrict__ scp, const float* __restrict__ sgp,
                          const float* __restrict__ Ap, const float* __restrict__ icp) {
    int i = blockIdx.x * blockDim.x + threadIdx.x;
    if (i >= NB * NPT) return;
    float scale = *scp, sigma = *sgp, A = *Ap, icc = *icp;
    float x = pts[i * 3 + 0], y = pts[i * 3 + 1], z = pts[i * 3 + 2];
    float r = fmaxf(sqrtf(x * x + y * y + z * z), 0.1f);
    float th = acosf(fminf(fmaxf(__fdividef(z, r), -1.f), 1.f));
    float ph = atan2f(y, x) + PI_F;
    float ct = th * (float)(RP / M_PI);
    float cp = ph * (float)(RP / (2.0 * M_PI));
    float cr = __fdividef(r, scale) * (float)RR;
    int it = min(max((int)floorf(ct), 0), RP - 1);
    int ip = min(max((int)floorf(cp), 0), RP - 1);
    int ir = min(max((int)floorf(cr), 0), RR - 1);
    float dt = ct - ((float)it + icc);
    float dp = cp - ((float)ip + icc);
    float dr = cr - ((float)ir + icc);
    float d2 = dt * dt + dp * dp + dr * dr;
    float w = A * __expf(-d2 * __fdividef(0.5f, sigma * sigma));
    int b = i >> 15;
    atomicAdd(&g_ft[((b * RR + ir) * RP + it) * RP + ip], w);
}

// ---------------- register-tiled 3x3 SAME conv + relu, 4-row tiles --------------
// block: 256 threads = (ocq=8 quads of 4 oc, row=4, colq=8 quads of 4 cols)
// covers 32 oc x 4 rows x 32 cols. grid: (8 rowtiles, OCT/32, 8 b).
// Weights come pre-transposed ([ic9][OCT]) so smem fill is coalesced.
template<int ICP, int PHASES, int ICT, int OCT>
__global__ void __launch_bounds__(256) k_conv(const float* __restrict__ in,
                                              const float* __restrict__ Wp,
                                              const float* __restrict__ bias,
                                              float* __restrict__ outp) {
    __shared__ __align__(16) float s_in[ICP * 6 * 36];
    __shared__ __align__(16) float s_w[ICP * 9 * 32];
    const int tid = threadIdx.x;
    const int rt = blockIdx.x;
    const int ocg = blockIdx.y;
    const int b = blockIdx.z;
    const int r0 = rt * 4;
    const int colq = tid & 7;
    const int row = (tid >> 3) & 3;
    const int ocq = tid >> 5;

    float acc[4][4];
    #pragma unroll
    for (int a = 0; a < 4; a++) {
        float bb = bias[ocg * 32 + ocq * 4 + a];
        #pragma unroll
        for (int k = 0; k < 4; k++) acc[a][k] = bb;
    }

    for (int ph = 0; ph < PHASES; ph++) {
        const int icb = ph * ICP;
        __syncthreads();
        for (int i = tid; i < ICP * 216; i += 256) {
            int ic = i / 216, rem = i % 216;
            int rr = rem / 36, cc = rem % 36;
            int X = r0 + rr - 1, Y = cc - 1;
            float v = 0.f;
            if (X >= 0 && X < 32 && Y >= 0 && Y < 32)
                v = in[((b * ICT + icb + ic) * 32 + X) * 32 + Y];
            s_in[i] = v;
        }
        // coalesced weight fill: s_w layout [ic][k9][32 oc]
        for (int i = tid; i < ICP * 288; i += 256) {
            int lin = i >> 5, oc = i & 31;                 // lin = ic*9 + k9
            s_w[i] = Wp[(icb * 9 + lin) * OCT + ocg * 32 + oc];
        }
        __syncthreads();
        #pragma unroll 1
        for (int ic = 0; ic < ICP; ic++) {
            #pragma unroll
            for (int dy = 0; dy < 3; dy++) {
                const float* irow = &s_in[(ic * 6 + row + dy) * 36 + colq * 4];
                float4 f0 = *(const float4*)irow;
                float2 f1 = *(const float2*)(irow + 4);
                float f[6] = {f0.x, f0.y, f0.z, f0.w, f1.x, f1.y};
                const float* wr = &s_w[(ic * 3 + dy) * 96 + ocq * 4];
                float4 w0 = *(const float4*)(wr);
                float4 w1 = *(const float4*)(wr + 32);
                float4 w2 = *(const float4*)(wr + 64);
                #pragma unroll
                for (int k = 0; k < 4; k++) {
                    acc[0][k] += f[k] * w0.x;     acc[1][k] += f[k] * w0.y;
                    acc[2][k] += f[k] * w0.z;     acc[3][k] += f[k] * w0.w;
                    acc[0][k] += f[k + 1] * w1.x; acc[1][k] += f[k + 1] * w1.y;
                    acc[2][k] += f[k + 1] * w1.z; acc[3][k] += f[k + 1] * w1.w;
                    acc[0][k] += f[k + 2] * w2.x; acc[1][k] += f[k + 2] * w2.y;
                    acc[2][k] += f[k + 2] * w2.z; acc[3][k] += f[k + 2] * w2.w;
                }
            }
        }
    }
    #pragma unroll
    for (int a = 0; a < 4; a++) {
        float4 vv = make_float4(fmaxf(acc[a][0], 0.f), fmaxf(acc[a][1], 0.f),
                                fmaxf(acc[a][2], 0.f), fmaxf(acc[a][3], 0.f));
        *(float4*)&outp[((b * OCT + ocg * 32 + ocq * 4 + a) * 32 + r0 + row) * 32 + colq * 4] = vv;
    }
}

// ---------------- ft_max[b,c] = (sum_xy h * wq[y]) * sum_g Wg[c,g] --------------
__global__ void k_ftmax(const float* __restrict__ Wg) {
    int bc = blockIdx.x;                  // 512
    int tid = threadIdx.x;                // 256
    const float* h = g_h2 + bc * 1024;
    float s = 0.f;
    for (int i = tid; i < 1024; i += 256) s += h[i] * g_wq[i & 31];
    __shared__ float red[8];
    for (int o = 16; o > 0; o >>= 1) s += __shfl_down_sync(0xffffffffu, s, o);
    if ((tid & 31) == 0) red[tid >> 5] = s;
    __syncthreads();
    if (tid == 0) {
        float tot = 0.f;
        for (int w = 0; w < 8; w++) tot += red[w];
        int c = bc & 63;
        float sw = 0.f;
        for (int g = 0; g < 32; g++) sw += Wg[c * 32 + g];
        g_ftmax[bc] = tot * sw;
    }
}

// ---------------- B[b,d] = b1[d] + sum_c W1[d, 64+c] * ftmax[b,c] ---------------
__global__ void k_bvec(const float* __restrict__ W1, const float* __restrict__ b1) {
    int i = threadIdx.x;                  // 512
    int b = i >> 6, d = i & 63;
    float s = b1[d];
    for (int c = 0; c < 64; c++) s += W1[d * 128 + 64 + c] * g_ftmax[b * 64 + c];
    g_Bvec[i] = s;
}

// ---------------- fused head, FFMA2, d split in two halves ----------------------
// Grid (64 pos-blocks of 16, 8 b). Warp owns 1 position per r-iter (2 iters).
// Per half: GEMM1 over 32 d -> 16 ull accs, relu in regs, GEMM2 partial into acc2.
__global__ void __launch_bounds__(256, 3) k_main(
    const float* __restrict__ W1, const float* __restrict__ Wg,
    const float* __restrict__ W2, const float* __restrict__ b2,
    float* __restrict__ out) {
    __shared__ __align__(16) float s_w1t[64 * 68];  // [c][d], pad 68
    __shared__ __align__(16) float s_w2t[64 * 36];  // [d][e], pad 36
    __shared__ float s_wg[64 * 32];                 // [c][g]
    __shared__ float s_h[64 * 16];                  // [c][p]
    __shared__ float s_B[64];
    __shared__ float s_b2[32];

    const int tid = threadIdx.x;
    const int w = tid >> 5, lane = tid & 31;
    const int b = blockIdx.y;
    const int pos0 = blockIdx.x * 16;

    for (int i = tid; i < 4096; i += 256) {
        int d = i >> 6, c = i & 63;
        s_w1t[c * 68 + d] = W1[d * 128 + c];
    }
    for (int i = tid; i < 2048; i += 256) {
        int e = i >> 6, d = i & 63;
        s_w2t[d * 36 + e] = W2[i];
    }
    for (int i = tid; i < 2048; i += 256) s_wg[i] = Wg[i];
    for (int i = tid; i < 1024; i += 256) {
        int c = i >> 4, p = i & 15;
        s_h[i] = g_h2[(b * 64 + c) * 1024 + pos0 + p];
    }
    if (tid < 64) s_B[tid] = g_Bvec[b * 64 + tid];
    if (tid < 32) s_b2[tid] = b2[tid];
    __syncthreads();

    for (int r = 0; r < 2; r++) {
        const int p = r * 8 + w;            // this warp's position (0..15)
        unsigned long long acc2[16];
        #pragma unroll
        for (int i = 0; i < 16; i++) acc2[i] = 0ull;

        #pragma unroll 1
        for (int h = 0; h < 2; h++) {
            // ---- GEMM1 half: P[d = h*32 .. h*32+31][g=lane] ----
            unsigned long long acc[16];
            #pragma unroll
            for (int i = 0; i < 16; i++) acc[i] = 0ull;
            #pragma unroll 2
            for (int c = 0; c < 64; c++) {
                float uv = s_wg[c * 32 + lane] * s_h[c * 16 + p];
                unsigned long long uvd = pack2(uv, uv);
                const ulonglong2* wrow = (const ulonglong2*)&s_w1t[c * 68 + h * 32];
                #pragma unroll
                for (int i = 0; i < 8; i++) {
                    ulonglong2 v = wrow[i];
                    acc[2 * i]     = ffma2(v.x, uvd, acc[2 * i]);
                    acc[2 * i + 1] = ffma2(v.y, uvd, acc[2 * i + 1]);
                }
            }
            // ---- relu(P + B) in place ----
            #pragma unroll
            for (int i = 0; i < 16; i++) {
                float lo, hi;
                unpack2(acc[i], lo, hi);
                lo = fmaxf(lo + s_B[h * 32 + 2 * i], 0.f);
                hi = fmaxf(hi + s_B[h * 32 + 2 * i + 1], 0.f);
                acc[i] = pack2(lo, hi);
            }
            // ---- GEMM2 partial: acc2[e pairs] += W2[:, d-half] @ relu ----
            #pragma unroll 2
            for (int i = 0; i < 16; i++) {
                float lo, hi;
                unpack2(acc[i], lo, hi);
                unsigned long long sd0 = pack2(lo, lo);
                unsigned long long sd1 = pack2(hi, hi);
                const int d0 = h * 32 + 2 * i;
                const ulonglong2* w2r0 = (const ulonglong2*)&s_w2t[d0 * 36];
                const ulonglong2* w2r1 = (const ulonglong2*)&s_w2t[(d0 + 1) * 36];
                #pragma unroll
                for (int j = 0; j < 8; j++) {
                    ulonglong2 v0 = w2r0[j];
                    acc2[2 * j]     = ffma2(v0.x, sd0, acc2[2 * j]);
                    acc2[2 * j + 1] = ffma2(v0.y, sd0, acc2[2 * j + 1]);
                }
                #pragma unroll
                for (int j = 0; j < 8; j++) {
                    ulonglong2 v1 = w2r1[j];
                    acc2[2 * j]     = ffma2(v1.x, sd1, acc2[2 * j]);
                    acc2[2 * j + 1] = ffma2(v1.y, sd1, acc2[2 * j + 1]);
                }
            }
        }
        // ---- epilogue: +b2, store (coalesced over g=lane) ----
        const int pos = pos0 + p;
        float* op = out + ((size_t)(b * 32) * 1024 + pos) * 32 + lane;
        #pragma unroll
        for (int j = 0; j < 16; j++) {
            float lo, hi;
            unpack2(acc2[j], lo, hi);
            lo += s_b2[2 * j];
            hi += s_b2[2 * j + 1];
            op[(size_t)(2 * j) * 32768]     = lo;
            op[(size_t)(2 * j + 1) * 32768] = hi;
        }
    }
}

// ---------------- ft_g: per (b,e) max over contiguous 32768 values ---------------
__global__ void k_ftg(const float* __restrict__ outv, float* __restrict__ tail) {
    int bc = blockIdx.x;                   // 256
    int tid = threadIdx.x;                 // 256
    const float4* p = (const float4*)(outv + (size_t)bc * 32768);
    float m = -3.4e38f;
    for (int i = tid; i < 8192; i += 256) {
        float4 v = p[i];
        m = fmaxf(m, fmaxf(fmaxf(v.x, v.y), fmaxf(v.z, v.w)));
    }
    __shared__ float red[8];
    for (int o = 16; o > 0; o >>= 1) m = fmaxf(m, __shfl_xor_sync(0xffffffffu, m, o));
    if ((tid & 31) == 0) red[tid >> 5] = m;
    __syncthreads();
    if (tid == 0) {
        for (int i = 1; i < 8; i++) m = fmaxf(m, red[i]);
        tail[bc] = m;
    }
}

// ---------------- launch --------------------------------------------------------
extern "C" void kernel_launch(void* const* d_in, const int* in_sizes, int n_in,
                              void* d_out, int out_size) {
    const float* pts   = (const float*)d_in[0];
    const float* scale = (const float*)d_in[1];
    const float* sigma = (const float*)d_in[2];
    const float* A     = (const float*)d_in[3];
    const float* icmp  = (const float*)d_in[4];
    int base = (n_in >= 16) ? 7 : 5;     // skip res_pt/res_r int scalars if present
    const float* Ws1 = (const float*)d_in[base + 0];
    const float* bs1 = (const float*)d_in[base + 1];
    const float* Ws2 = (const float*)d_in[base + 2];
    const float* bs2 = (const float*)d_in[base + 3];
    const float* Wg  = (const float*)d_in[base + 4];
    const float* W1  = (const float*)d_in[base + 5];
    const float* b1  = (const float*)d_in[base + 6];
    const float* W2  = (const float*)d_in[base + 7];
    const float* b2  = (const float*)d_in[base + 8];
    float* out = (float*)d_out;

    float *ftp = nullptr, *h1p = nullptr, *h2p = nullptr, *wc1p = nullptr, *wc2p = nullptr;
    cudaGetSymbolAddress((void**)&ftp, g_ft);
    cudaGetSymbolAddress((void**)&h1p, g_h1);
    cudaGetSymbolAddress((void**)&h2p, g_h2);
    cudaGetSymbolAddress((void**)&wc1p, g_wc1);
    cudaGetSymbolAddress((void**)&wc2p, g_wc2);

    k_init<<<256, 256>>>();
    k_wprep<<<72, 256>>>(Ws1, Ws2);
    k_scatter<<<(NB * NPT + 255) / 256, 256>>>(pts, scale, sigma, A, icmp);
    k_conv<8, 1, 8, 32><<<dim3(8, 1, 8), 256>>>(ftp, wc1p, bs1, h1p);
    k_conv<16, 2, 32, 64><<<dim3(8, 2, 8), 256>>>(h1p, wc2p, bs2, h2p);
    k_ftmax<<<512, 256>>>(Wg);
    k_bvec<<<1, 512>>>(W1, b1);
    k_main<<<dim3(64, NB), 256>>>(W1, Wg, W2, b2, out);
    k_ftg<<<256, 256>>>(out, out + (size_t)NB * 32 * 1024 * 32);
}

// round 7
// speedup vs baseline: 1.5966x; 1.5966x over previous
#include <cuda_runtime.h>
#include <math.h>

#define RP 32
#define RR 8
#define NB 8
#define NPT 32768
#define PI_F 3.14159265358979323846f

// ---------------- scratch (device globals; no allocation allowed) ----------------
__device__ float g_ft[NB * RR * RP * RP];     // (b, r, theta, phi)
__device__ float g_h1[NB * 32 * RP * RP];     // conv1 out
__device__ float g_h2[NB * 64 * RP * RP];     // conv2 out
__device__ float g_ftmax[NB * 64];
__device__ float g_Bvec[NB * 64];
__device__ float g_wq[RP];
__device__ float g_wc1[8 * 9 * 32];           // conv1 weights, [ic*9+k9][oc]
__device__ float g_wc2[32 * 9 * 64];          // conv2 weights, [ic*9+k9][oc]
__device__ float g_w1t[64 * 64];              // W1 head transposed: [c][d]
__device__ unsigned long long g_w2d[64 * 32]; // W2 head dup: [d][e] = {v,v}

// ---------------- f32x2 packed helpers ------------------------------------------
__device__ __forceinline__ unsigned long long ffma2(unsigned long long a,
                                                    unsigned long long b,
                                                    unsigned long long c) {
    unsigned long long d;
    asm("fma.rn.f32x2 %0, %1, %2, %3;" : "=l"(d) : "l"(a), "l"(b), "l"(c));
    return d;
}
__device__ __forceinline__ unsigned long long pack2(float lo, float hi) {
    unsigned long long d;
    asm("mov.b64 %0, {%1, %2};" : "=l"(d) : "f"(lo), "f"(hi));
    return d;
}
__device__ __forceinline__ void unpack2(unsigned long long v, float& lo, float& hi) {
    asm("mov.b64 {%0, %1}, %2;" : "=f"(lo), "=f"(hi) : "l"(v));
}

// ---------------- init: zero grid, quadrature weights, weight re-layouts ---------
__global__ void k_init(const float* __restrict__ Wc1, const float* __restrict__ Wc2,
                       const float* __restrict__ W1h, const float* __restrict__ W2h) {
    int i = blockIdx.x * blockDim.x + threadIdx.x;   // 65536 threads
    g_ft[i] = 0.f;                                   // exactly covers 65536
    if (i < RP) {
        double jj = (double)i;
        double theta = M_PI * (2.0 * jj + 1.0) / 64.0;
        double s = 0.0;
        for (int k = 0; k < 16; k++)
            s += sin((2.0 * jj + 1.0) * (2.0 * k + 1.0) * M_PI / 64.0) / (2.0 * k + 1.0);
        g_wq[i] = (float)((2.0 / 16.0) * sin(theta) * s);
    }
    if (i < 8 * 9 * 32) {                            // conv1 weights transpose
        int ic9 = i >> 5, oc = i & 31;
        g_wc1[i] = Wc1[oc * 72 + ic9];
    }
    if (i < 32 * 9 * 64) {                           // conv2 weights transpose
        int ic9 = i >> 6, oc = i & 63;
        g_wc2[i] = Wc2[oc * 288 + ic9];
    }
    if (i < 4096) {                                  // head W1 transpose [c][d]
        int c = i >> 6, d = i & 63;
        g_w1t[i] = W1h[d * 128 + c];
    }
    if (i < 2048) {                                  // head W2 dup [d][e]
        int d = i >> 5, e = i & 31;
        float v = W2h[e * 64 + d];
        g_w2d[i] = pack2(v, v);
    }
}

// ---------------- scatter: gaussian splat of w into (b, r, t, p) grid ------------
__global__ void __launch_bounds__(256) k_scatter(const float* __restrict__ pts,
                          const float* __restrict__ scp, const float* __restrict__ sgp,
                          const float* __restrict__ Ap, const float* __restrict__ icp) {
    int i = blockIdx.x * blockDim.x + threadIdx.x;
    if (i >= NB * NPT) return;
    float scale = *scp, sigma = *sgp, A = *Ap, icc = *icp;
    float x = pts[i * 3 + 0], y = pts[i * 3 + 1], z = pts[i * 3 + 2];
    float r = fmaxf(sqrtf(x * x + y * y + z * z), 0.1f);
    float th = acosf(fminf(fmaxf(__fdividef(z, r), -1.f), 1.f));
    float ph = atan2f(y, x) + PI_F;
    float ct = th * (float)(RP / M_PI);
    float cp = ph * (float)(RP / (2.0 * M_PI));
    float cr = __fdividef(r, scale) * (float)RR;
    int it = min(max((int)floorf(ct), 0), RP - 1);
    int ip = min(max((int)floorf(cp), 0), RP - 1);
    int ir = min(max((int)floorf(cr), 0), RR - 1);
    float dt = ct - ((float)it + icc);
    float dp = cp - ((float)ip + icc);
    float dr = cr - ((float)ir + icc);
    float d2 = dt * dt + dp * dp + dr * dr;
    float w = A * __expf(-d2 * __fdividef(0.5f, sigma * sigma));
    int b = i >> 15;
    atomicAdd(&g_ft[((b * RR + ir) * RP + it) * RP + ip], w);
}

// ---------------- register-tiled 3x3 SAME conv + relu ---------------------------
// TR rows per tile, TR cols per thread. 256 threads = ocq(8)*row(TR)*colq(32/TR).
// grid: (32/TR rowtiles, OCT/32, 8 b). Weights pre-transposed [ic9][OCT].
template<int ICP, int PHASES, int ICT, int OCT, int TR>
__global__ void __launch_bounds__(256) k_conv(const float* __restrict__ in,
                                              const float* __restrict__ Wp,
                                              const float* __restrict__ bias,
                                              float* __restrict__ outp) {
    __shared__ __align__(16) float s_in[ICP * (TR + 2) * 36];
    __shared__ __align__(16) float s_w[ICP * 9 * 32];
    constexpr int NCQ = 32 / TR;                     // col quads
    const int tid = threadIdx.x;
    const int rt = blockIdx.x;
    const int ocg = blockIdx.y;
    const int b = blockIdx.z;
    const int r0 = rt * TR;
    const int colq = tid & (NCQ - 1);
    const int row = (tid / NCQ) & (TR - 1);
    const int ocq = tid >> 5;

    float acc[4][TR];
    #pragma unroll
    for (int a = 0; a < 4; a++) {
        float bb = bias[ocg * 32 + ocq * 4 + a];
        #pragma unroll
        for (int k = 0; k < TR; k++) acc[a][k] = bb;
    }

    for (int ph = 0; ph < PHASES; ph++) {
        const int icb = ph * ICP;
        __syncthreads();
        for (int i = tid; i < ICP * (TR + 2) * 36; i += 256) {
            int ic = i / ((TR + 2) * 36), rem = i % ((TR + 2) * 36);
            int rr = rem / 36, cc = rem % 36;
            int X = r0 + rr - 1, Y = cc - 1;
            float v = 0.f;
            if (X >= 0 && X < 32 && Y >= 0 && Y < 32)
                v = in[((b * ICT + icb + ic) * 32 + X) * 32 + Y];
            s_in[i] = v;
        }
        for (int i = tid; i < ICP * 288; i += 256) {   // coalesced: [ic][k9][32 oc]
            int lin = i >> 5, oc = i & 31;
            s_w[i] = Wp[(icb * 9 + lin) * OCT + ocg * 32 + oc];
        }
        __syncthreads();
        #pragma unroll 1
        for (int ic = 0; ic < ICP; ic++) {
            #pragma unroll
            for (int dy = 0; dy < 3; dy++) {
                const float* irow = &s_in[(ic * (TR + 2) + row + dy) * 36 + colq * TR];
                float f[TR + 2];
                if (TR == 4) {
                    float4 f0 = *(const float4*)irow;
                    float2 f1 = *(const float2*)(irow + 4);
                    f[0] = f0.x; f[1] = f0.y; f[2] = f0.z; f[3] = f0.w;
                    f[4] = f1.x; f[5] = f1.y;
                } else {
                    float2 f0 = *(const float2*)irow;
                    float2 f1 = *(const float2*)(irow + 2);
                    f[0] = f0.x; f[1] = f0.y; f[2] = f1.x; f[3] = f1.y;
                }
                const float* wr = &s_w[(ic * 3 + dy) * 96 + ocq * 4];
                float4 w0 = *(const float4*)(wr);
                float4 w1 = *(const float4*)(wr + 32);
                float4 w2 = *(const float4*)(wr + 64);
                #pragma unroll
                for (int k = 0; k < TR; k++) {
                    acc[0][k] += f[k] * w0.x;     acc[1][k] += f[k] * w0.y;
                    acc[2][k] += f[k] * w0.z;     acc[3][k] += f[k] * w0.w;
                    acc[0][k] += f[k + 1] * w1.x; acc[1][k] += f[k + 1] * w1.y;
                    acc[2][k] += f[k + 1] * w1.z; acc[3][k] += f[k + 1] * w1.w;
                    acc[0][k] += f[k + 2] * w2.x; acc[1][k] += f[k + 2] * w2.y;
                    acc[2][k] += f[k + 2] * w2.z; acc[3][k] += f[k + 2] * w2.w;
                }
            }
        }
    }
    #pragma unroll
    for (int a = 0; a < 4; a++) {
        float* dst = &outp[((b * OCT + ocg * 32 + ocq * 4 + a) * 32 + r0 + row) * 32 + colq * TR];
        if (TR == 4) {
            float4 vv = make_float4(fmaxf(acc[a][0], 0.f), fmaxf(acc[a][1], 0.f),
                                    fmaxf(acc[a][2], 0.f), fmaxf(acc[a][3], 0.f));
            *(float4*)dst = vv;
        } else {
            float2 vv = make_float2(fmaxf(acc[a][0], 0.f), fmaxf(acc[a][1], 0.f));
            *(float2*)dst = vv;
        }
    }
}

// ---------------- ft_max[b,c] = (sum_xy h * wq[y]) * sum_g Wg[c,g] --------------
__global__ void k_ftmax(const float* __restrict__ Wg) {
    int bc = blockIdx.x;                  // 512
    int tid = threadIdx.x;                // 256
    const float* h = g_h2 + bc * 1024;
    float s = 0.f;
    for (int i = tid; i < 1024; i += 256) s += h[i] * g_wq[i & 31];
    __shared__ float red[8];
    for (int o = 16; o > 0; o >>= 1) s += __shfl_down_sync(0xffffffffu, s, o);
    if ((tid & 31) == 0) red[tid >> 5] = s;
    __syncthreads();
    if (tid == 0) {
        float tot = 0.f;
        for (int w = 0; w < 8; w++) tot += red[w];
        int c = bc & 63;
        float sw = 0.f;
        for (int g = 0; g < 32; g++) sw += Wg[c * 32 + g];
        g_ftmax[bc] = tot * sw;
    }
}

// ---------------- B[b,d] = b1[d] + sum_c W1[d, 64+c] * ftmax[b,c] ---------------
__global__ void k_bvec(const float* __restrict__ W1, const float* __restrict__ b1) {
    int i = threadIdx.x;                  // 512
    int b = i >> 6, d = i & 63;
    float s = b1[d];
    for (int c = 0; c < 64; c++) s += W1[d * 128 + 64 + c] * g_ftmax[b * 64 + c];
    g_Bvec[i] = s;
}

// ---------------- fused head: register-tiled GEMM over n = (xy, g) --------------
// Block: 8 xy positions -> n-tile 256 (n = xy_local*32 + g). 256 threads.
// GEMM1: D1[64d, 256n] = W1t^T @ U, thread tile 16d x 4n (acc = 32 ull d-pairs).
// relu(+B) -> smem (reusing U). GEMM2: out[32e, 256n], thread tile 8e x 4n.
#define SMEM_MAIN (65536 + 16384 + 16384 + 256 + 128)
__global__ void __launch_bounds__(256, 2) k_main(
    const float* __restrict__ Wg, const float* __restrict__ b2,
    float* __restrict__ out) {
    extern __shared__ __align__(16) char dsm[];
    float* s_u = (float*)dsm;                                   // 64c x 256n (also D1 as [d][n])
    float* s_w1t = (float*)(dsm + 65536);                       // [c][64 d]
    unsigned long long* s_w2d = (unsigned long long*)(dsm + 65536 + 16384);  // [d][32 e] dup
    float* s_B = (float*)(dsm + 65536 + 32768);
    float* s_b2 = s_B + 64;

    const int tid = threadIdx.x;
    const int b = blockIdx.y;
    const int pos0 = blockIdx.x * 8;     // 8 xy per block

    // ---- fills (all coalesced) ----
    {
        const float4* src1 = (const float4*)g_w1t;
        float4* dst1 = (float4*)s_w1t;
        #pragma unroll
        for (int i = 0; i < 4; i++) dst1[tid + i * 256] = src1[tid + i * 256];
        const float4* src2 = (const float4*)g_w2d;
        float4* dst2 = (float4*)s_w2d;
        #pragma unroll
        for (int i = 0; i < 4; i++) dst2[tid + i * 256] = src2[tid + i * 256];
    }
    if (tid < 64) s_B[tid] = g_Bvec[b * 64 + tid];
    if (tid < 32) s_b2[tid] = b2[tid];
    // ---- build U[c][n] = h[c, xy] * Wg[c, g] ----
    #pragma unroll 4
    for (int i = tid; i < 16384; i += 256) {
        int c = i >> 8, nl = i & 255;
        s_u[i] = g_h2[(b * 64 + c) * 1024 + pos0 + (nl >> 5)] * Wg[c * 32 + (nl & 31)];
    }
    __syncthreads();

    // ---- GEMM1: thread (dgrp = tid>>6 -> 16 d, ngrp = tid&63 -> 4 n) ----
    const int n0 = (tid & 63) * 4;
    const int d0 = (tid >> 6) * 16;
    unsigned long long acc[8][4];
    #pragma unroll
    for (int i = 0; i < 8; i++)
        #pragma unroll
        for (int j = 0; j < 4; j++) acc[i][j] = 0ull;

    {
        const float* up = s_u + n0;
        const float* wp = s_w1t + d0;
        #pragma unroll 2
        for (int c = 0; c < 64; c++) {
            float4 u4 = *(const float4*)(up + c * 256);
            unsigned long long ud0 = pack2(u4.x, u4.x);
            unsigned long long ud1 = pack2(u4.y, u4.y);
            unsigned long long ud2 = pack2(u4.z, u4.z);
            unsigned long long ud3 = pack2(u4.w, u4.w);
            const ulonglong2* wr = (const ulonglong2*)(wp + c * 64);
            #pragma unroll
            for (int i = 0; i < 4; i++) {
                ulonglong2 wv = wr[i];
                acc[2 * i][0] = ffma2(wv.x, ud0, acc[2 * i][0]);
                acc[2 * i][1] = ffma2(wv.x, ud1, acc[2 * i][1]);
                acc[2 * i][2] = ffma2(wv.x, ud2, acc[2 * i][2]);
                acc[2 * i][3] = ffma2(wv.x, ud3, acc[2 * i][3]);
                acc[2 * i + 1][0] = ffma2(wv.y, ud0, acc[2 * i + 1][0]);
                acc[2 * i + 1][1] = ffma2(wv.y, ud1, acc[2 * i + 1][1]);
                acc[2 * i + 1][2] = ffma2(wv.y, ud2, acc[2 * i + 1][2]);
                acc[2 * i + 1][3] = ffma2(wv.y, ud3, acc[2 * i + 1][3]);
            }
        }
    }
    __syncthreads();   // all reads of s_u done before overwrite

    // ---- relu(D1 + B) -> s_d1 (= s_u region, [d][256 n]) ----
    #pragma unroll
    for (int i = 0; i < 8; i++) {
        int d = d0 + 2 * i;
        float blo = s_B[d], bhi = s_B[d + 1];
        #pragma unroll
        for (int j = 0; j < 4; j++) {
            float lo, hi;
            unpack2(acc[i][j], lo, hi);
            s_u[d * 256 + n0 + j] = fmaxf(lo + blo, 0.f);
            s_u[(d + 1) * 256 + n0 + j] = fmaxf(hi + bhi, 0.f);
        }
    }
    __syncthreads();

    // ---- GEMM2: thread (egrp = tid>>6 -> 8 e, same 4 n) ----
    const int e0 = (tid >> 6) * 8;
    unsigned long long acc2[8][2];
    #pragma unroll
    for (int i = 0; i < 8; i++) { acc2[i][0] = 0ull; acc2[i][1] = 0ull; }
    {
        const float* dp = s_u + n0;
        const unsigned long long* wp2 = s_w2d + e0;
        #pragma unroll 2
        for (int d = 0; d < 64; d++) {
            ulonglong2 uu = *(const ulonglong2*)(dp + d * 256);   // 2 natural n-pairs
            const ulonglong2* wd = (const ulonglong2*)(wp2 + d * 32);
            #pragma unroll
            for (int i = 0; i < 4; i++) {
                ulonglong2 wv = wd[i];
                acc2[2 * i][0] = ffma2(wv.x, uu.x, acc2[2 * i][0]);
                acc2[2 * i][1] = ffma2(wv.x, uu.y, acc2[2 * i][1]);
                acc2[2 * i + 1][0] = ffma2(wv.y, uu.x, acc2[2 * i + 1][0]);
                acc2[2 * i + 1][1] = ffma2(wv.y, uu.y, acc2[2 * i + 1][1]);
            }
        }
    }

    // ---- epilogue: +b2, vectorized store ----
    const int xy = pos0 + (n0 >> 5);
    const int g0 = n0 & 31;
    #pragma unroll
    for (int e = 0; e < 8; e++) {
        float v0, v1, v2, v3;
        unpack2(acc2[e][0], v0, v1);
        unpack2(acc2[e][1], v2, v3);
        float bb = s_b2[e0 + e];
        float4 vv = make_float4(v0 + bb, v1 + bb, v2 + bb, v3 + bb);
        *(float4*)&out[(((size_t)b * 32 + e0 + e) * 1024 + xy) * 32 + g0] = vv;
    }
}

// ---------------- ft_g: per (b,e) max over contiguous 32768 values ---------------
__global__ void k_ftg(const float* __restrict__ outv, float* __restrict__ tail) {
    int bc = blockIdx.x;                   // 256
    int tid = threadIdx.x;                 // 256
    const float4* p = (const float4*)(outv + (size_t)bc * 32768);
    float m = -3.4e38f;
    for (int i = tid; i < 8192; i += 256) {
        float4 v = p[i];
        m = fmaxf(m, fmaxf(fmaxf(v.x, v.y), fmaxf(v.z, v.w)));
    }
    __shared__ float red[8];
    for (int o = 16; o > 0; o >>= 1) m = fmaxf(m, __shfl_xor_sync(0xffffffffu, m, o));
    if ((tid & 31) == 0) red[tid >> 5] = m;
    __syncthreads();
    if (tid == 0) {
        for (int i = 1; i < 8; i++) m = fmaxf(m, red[i]);
        tail[bc] = m;
    }
}

// ---------------- launch --------------------------------------------------------
extern "C" void kernel_launch(void* const* d_in, const int* in_sizes, int n_in,
                              void* d_out, int out_size) {
    const float* pts   = (const float*)d_in[0];
    const float* scale = (const float*)d_in[1];
    const float* sigma = (const float*)d_in[2];
    const float* A     = (const float*)d_in[3];
    const float* icmp  = (const float*)d_in[4];
    int base = (n_in >= 16) ? 7 : 5;     // skip res_pt/res_r int scalars if present
    const float* Ws1 = (const float*)d_in[base + 0];
    const float* bs1 = (const float*)d_in[base + 1];
    const float* Ws2 = (const float*)d_in[base + 2];
    const float* bs2 = (const float*)d_in[base + 3];
    const float* Wg  = (const float*)d_in[base + 4];
    const float* W1  = (const float*)d_in[base + 5];
    const float* b1  = (const float*)d_in[base + 6];
    const float* W2  = (const float*)d_in[base + 7];
    const float* b2  = (const float*)d_in[base + 8];
    float* out = (float*)d_out;

    float *ftp = nullptr, *h1p = nullptr, *h2p = nullptr, *wc1p = nullptr, *wc2p = nullptr;
    cudaGetSymbolAddress((void**)&ftp, g_ft);
    cudaGetSymbolAddress((void**)&h1p, g_h1);
    cudaGetSymbolAddress((void**)&h2p, g_h2);
    cudaGetSymbolAddress((void**)&wc1p, g_wc1);
    cudaGetSymbolAddress((void**)&wc2p, g_wc2);

    static int attr_done = 0;
    if (!attr_done) {
        cudaFuncSetAttribute(k_main, cudaFuncAttributeMaxDynamicSharedMemorySize, SMEM_MAIN);
        attr_done = 1;
    }

    k_init<<<256, 256>>>(Ws1, Ws2, W1, W2);
    k_scatter<<<(NB * NPT + 255) / 256, 256>>>(pts, scale, sigma, A, icmp);
    k_conv<8, 1, 8, 32, 2><<<dim3(16, 1, 8), 256>>>(ftp, wc1p, bs1, h1p);
    k_conv<16, 2, 32, 64, 4><<<dim3(8, 2, 8), 256>>>(h1p, wc2p, bs2, h2p);
    k_ftmax<<<512, 256>>>(Wg);
    k_bvec<<<1, 512>>>(W1, b1);
    k_main<<<dim3(128, NB), 256, SMEM_MAIN>>>(Wg, b2, out);
    k_ftg<<<256, 256>>>(out, out + (size_t)NB * 32 * 1024 * 32);
}

// round 8
// speedup vs baseline: 1.6140x; 1.0109x over previous
#include <cuda_runtime.h>
#include <math.h>

#define RP 32
#define RR 8
#define NB 8
#define NPT 32768
#define PI_F 3.14159265358979323846f

// ---------------- scratch (device globals; no allocation allowed) ----------------
__device__ float g_ft[NB * RR * RP * RP];     // (b, r, theta, phi)
__device__ float g_h1[NB * 32 * RP * RP];     // conv1 out
__device__ float g_h2[NB * 64 * RP * RP];     // conv2 out
__device__ float g_ftmax[NB * 64];
__device__ float g_Bvec[NB * 64];
__device__ float g_wq[RP];
__device__ float g_wc1[8 * 9 * 32];           // conv1 weights, [ic*9+k9][oc]
__device__ float g_wc2[32 * 9 * 64];          // conv2 weights, [ic*9+k9][oc]
__device__ float g_w1t[64 * 64];              // W1 head transposed: [c][d]
__device__ unsigned long long g_w2d[64 * 32]; // W2 head dup: [d][e] = {v,v}

// ---------------- f32x2 packed helpers ------------------------------------------
__device__ __forceinline__ unsigned long long ffma2(unsigned long long a,
                                                    unsigned long long b,
                                                    unsigned long long c) {
    unsigned long long d;
    asm("fma.rn.f32x2 %0, %1, %2, %3;" : "=l"(d) : "l"(a), "l"(b), "l"(c));
    return d;
}
__device__ __forceinline__ unsigned long long pack2(float lo, float hi) {
    unsigned long long d;
    asm("mov.b64 %0, {%1, %2};" : "=l"(d) : "f"(lo), "f"(hi));
    return d;
}
__device__ __forceinline__ void unpack2(unsigned long long v, float& lo, float& hi) {
    asm("mov.b64 {%0, %1}, %2;" : "=f"(lo), "=f"(hi) : "l"(v));
}

// ---------------- init: zero grid, quadrature weights, weight re-layouts ---------
__global__ void k_init(const float* __restrict__ Wc1, const float* __restrict__ Wc2,
                       const float* __restrict__ W1h, const float* __restrict__ W2h) {
    int i = blockIdx.x * blockDim.x + threadIdx.x;   // 65536 threads
    g_ft[i] = 0.f;                                   // exactly covers 65536
    if (i < RP) {
        double jj = (double)i;
        double theta = M_PI * (2.0 * jj + 1.0) / 64.0;
        double s = 0.0;
        for (int k = 0; k < 16; k++)
            s += sin((2.0 * jj + 1.0) * (2.0 * k + 1.0) * M_PI / 64.0) / (2.0 * k + 1.0);
        g_wq[i] = (float)((2.0 / 16.0) * sin(theta) * s);
    }
    if (i < 8 * 9 * 32) {                            // conv1 weights transpose
        int ic9 = i >> 5, oc = i & 31;
        g_wc1[i] = Wc1[oc * 72 + ic9];
    }
    if (i < 32 * 9 * 64) {                           // conv2 weights transpose
        int ic9 = i >> 6, oc = i & 63;
        g_wc2[i] = Wc2[oc * 288 + ic9];
    }
    if (i < 4096) {                                  // head W1 transpose [c][d]
        int c = i >> 6, d = i & 63;
        g_w1t[i] = W1h[d * 128 + c];
    }
    if (i < 2048) {                                  // head W2 dup [d][e]
        int d = i >> 5, e = i & 31;
        float v = W2h[e * 64 + d];
        g_w2d[i] = pack2(v, v);
    }
}

// ---------------- scatter: gaussian splat of w into (b, r, t, p) grid ------------
__global__ void __launch_bounds__(256) k_scatter(const float* __restrict__ pts,
                          const float* __restrict__ scp, const float* __restrict__ sgp,
                          const float* __restrict__ Ap, const float* __restrict__ icp) {
    int i = blockIdx.x * blockDim.x + threadIdx.x;
    if (i >= NB * NPT) return;
    float scale = *scp, sigma = *sgp, A = *Ap, icc = *icp;
    float x = pts[i * 3 + 0], y = pts[i * 3 + 1], z = pts[i * 3 + 2];
    float r = fmaxf(sqrtf(x * x + y * y + z * z), 0.1f);
    float th = acosf(fminf(fmaxf(__fdividef(z, r), -1.f), 1.f));
    float ph = atan2f(y, x) + PI_F;
    float ct = th * (float)(RP / M_PI);
    float cp = ph * (float)(RP / (2.0 * M_PI));
    float cr = __fdividef(r, scale) * (float)RR;
    int it = min(max((int)floorf(ct), 0), RP - 1);
    int ip = min(max((int)floorf(cp), 0), RP - 1);
    int ir = min(max((int)floorf(cr), 0), RR - 1);
    float dt = ct - ((float)it + icc);
    float dp = cp - ((float)ip + icc);
    float dr = cr - ((float)ir + icc);
    float d2 = dt * dt + dp * dp + dr * dr;
    float w = A * __expf(-d2 * __fdividef(0.5f, sigma * sigma));
    int b = i >> 15;
    atomicAdd(&g_ft[((b * RR + ir) * RP + it) * RP + ip], w);
}

// ---------------- implicit-GEMM 3x3 SAME conv + relu, f32x2 oc-packed -----------
// Thread tile: 4 oc (2 ull pairs) x 4 cols. blockDim = 8 * NGRP, NGRP = ROWS*8.
// a-operand = weight pair (2 consecutive oc floats) -> warp-uniform LDS.128.
// b-operand = input value duplicated via pack2, shared across all oc.
// grid: (32/ROWS rowtiles, OCT/OCB, NB). Weights pre-transposed [ic9][OCT].
template<int ICT, int OCT, int OCB, int ROWS, int NGRP>
__global__ void k_cgemm(const float* __restrict__ in,
                        const float* __restrict__ Wp,
                        const float* __restrict__ bias,
                        float* __restrict__ outp) {
    extern __shared__ __align__(16) float sm[];
    float* s_in = sm;                                  // [ICT][ROWS+2][40]
    float* s_w = sm + ICT * (ROWS + 2) * 40;           // [ICT*9][OCB]
    const int tid = threadIdx.x;
    const int nthr = 8 * NGRP;
    const int rt = blockIdx.x;
    const int ocg = blockIdx.y;
    const int b = blockIdx.z;
    const int r0 = rt * ROWS;

    const int ng = tid % NGRP;
    const int ocq = tid / NGRP;
    const int n0 = ng * 4;
    const int rr = n0 >> 5;           // local row
    const int c0 = n0 & 31;           // first of 4 cols (multiple of 4)
    const int op0 = ocq * 4;          // first of 4 oc

    // ---- fills ----
    for (int i = tid; i < ICT * (ROWS + 2) * 40; i += nthr) {
        int ic = i / ((ROWS + 2) * 40), rem = i % ((ROWS + 2) * 40);
        int r = rem / 40, cc = rem % 40;
        int X = r0 + r - 1, Y = cc - 1;
        float v = 0.f;
        if (X >= 0 && X < 32 && Y >= 0 && Y < 32)
            v = in[((b * ICT + ic) * 32 + X) * 32 + Y];
        s_in[i] = v;
    }
    {
        float4* dst = (float4*)s_w;
        const int nf4 = ICT * 9 * OCB / 4;
        for (int i = tid; i < nf4; i += nthr) {
            int k = i / (OCB / 4), o4 = i % (OCB / 4);
            dst[i] = *(const float4*)&Wp[k * OCT + ocg * OCB + o4 * 4];
        }
    }

    // ---- accs init with bias ----
    unsigned long long acc[2][4];
    {
        float b0 = bias[ocg * OCB + op0 + 0], b1 = bias[ocg * OCB + op0 + 1];
        float b2_ = bias[ocg * OCB + op0 + 2], b3 = bias[ocg * OCB + op0 + 3];
        unsigned long long p0 = pack2(b0, b1), p1 = pack2(b2_, b3);
        #pragma unroll
        for (int j = 0; j < 4; j++) { acc[0][j] = p0; acc[1][j] = p1; }
    }
    __syncthreads();

    // ---- mainloop ----
    #pragma unroll 1
    for (int ic = 0; ic < ICT; ic++) {
        #pragma unroll
        for (int dy = 0; dy < 3; dy++) {
            const float* fp = &s_in[(ic * (ROWS + 2) + rr + dy) * 40 + c0];
            float4 fa = *(const float4*)fp;
            float2 fb = *(const float2*)(fp + 4);
            unsigned long long dup[6];
            dup[0] = pack2(fa.x, fa.x); dup[1] = pack2(fa.y, fa.y);
            dup[2] = pack2(fa.z, fa.z); dup[3] = pack2(fa.w, fa.w);
            dup[4] = pack2(fb.x, fb.x); dup[5] = pack2(fb.y, fb.y);
            #pragma unroll
            for (int dx = 0; dx < 3; dx++) {
                int k = ic * 9 + dy * 3 + dx;
                ulonglong2 wv = *(const ulonglong2*)&s_w[k * OCB + op0];
                #pragma unroll
                for (int j = 0; j < 4; j++) {
                    acc[0][j] = ffma2(wv.x, dup[j + dx], acc[0][j]);
                    acc[1][j] = ffma2(wv.y, dup[j + dx], acc[1][j]);
                }
            }
        }
    }

    // ---- epilogue: relu + store (float4 per oc over 4 cols) ----
    float v[4][4];
    #pragma unroll
    for (int p = 0; p < 2; p++)
        #pragma unroll
        for (int j = 0; j < 4; j++) {
            float lo, hi;
            unpack2(acc[p][j], lo, hi);
            v[2 * p][j] = fmaxf(lo, 0.f);
            v[2 * p + 1][j] = fmaxf(hi, 0.f);
        }
    #pragma unroll
    for (int o = 0; o < 4; o++) {
        float4 vv = make_float4(v[o][0], v[o][1], v[o][2], v[o][3]);
        *(float4*)&outp[((b * OCT + ocg * OCB + op0 + o) * 32 + r0 + rr) * 32 + c0] = vv;
    }
}

// ---------------- ft_max[b,c] = (sum_xy h * wq[y]) * sum_g Wg[c,g] --------------
__global__ void k_ftmax(const float* __restrict__ Wg) {
    int bc = blockIdx.x;                  // 512
    int tid = threadIdx.x;                // 256
    const float* h = g_h2 + bc * 1024;
    float s = 0.f;
    for (int i = tid; i < 1024; i += 256) s += h[i] * g_wq[i & 31];
    __shared__ float red[8];
    for (int o = 16; o > 0; o >>= 1) s += __shfl_down_sync(0xffffffffu, s, o);
    if ((tid & 31) == 0) red[tid >> 5] = s;
    __syncthreads();
    if (tid == 0) {
        float tot = 0.f;
        for (int w = 0; w < 8; w++) tot += red[w];
        int c = bc & 63;
        float sw = 0.f;
        for (int g = 0; g < 32; g++) sw += Wg[c * 32 + g];
        g_ftmax[bc] = tot * sw;
    }
}

// ---------------- B[b,d] = b1[d] + sum_c W1[d, 64+c] * ftmax[b,c] ---------------
__global__ void k_bvec(const float* __restrict__ W1, const float* __restrict__ b1) {
    int i = threadIdx.x;                  // 512
    int b = i >> 6, d = i & 63;
    float s = b1[d];
    for (int c = 0; c < 64; c++) s += W1[d * 128 + 64 + c] * g_ftmax[b * 64 + c];
    g_Bvec[i] = s;
}

// ---------------- fused head: register-tiled GEMM over n = (xy, g) --------------
#define SMEM_MAIN (65536 + 16384 + 16384 + 256 + 128)
__global__ void __launch_bounds__(256, 2) k_main(
    const float* __restrict__ Wg, const float* __restrict__ b2,
    float* __restrict__ out) {
    extern __shared__ __align__(16) char dsm[];
    float* s_u = (float*)dsm;                                   // 64c x 256n (also D1 as [d][n])
    float* s_w1t = (float*)(dsm + 65536);                       // [c][64 d]
    unsigned long long* s_w2d = (unsigned long long*)(dsm + 65536 + 16384);  // [d][32 e] dup
    float* s_B = (float*)(dsm + 65536 + 32768);
    float* s_b2 = s_B + 64;

    const int tid = threadIdx.x;
    const int b = blockIdx.y;
    const int pos0 = blockIdx.x * 8;     // 8 xy per block

    {
        const float4* src1 = (const float4*)g_w1t;
        float4* dst1 = (float4*)s_w1t;
        #pragma unroll
        for (int i = 0; i < 4; i++) dst1[tid + i * 256] = src1[tid + i * 256];
        const float4* src2 = (const float4*)g_w2d;
        float4* dst2 = (float4*)s_w2d;
        #pragma unroll
        for (int i = 0; i < 4; i++) dst2[tid + i * 256] = src2[tid + i * 256];
    }
    if (tid < 64) s_B[tid] = g_Bvec[b * 64 + tid];
    if (tid < 32) s_b2[tid] = b2[tid];
    #pragma unroll 4
    for (int i = tid; i < 16384; i += 256) {
        int c = i >> 8, nl = i & 255;
        s_u[i] = g_h2[(b * 64 + c) * 1024 + pos0 + (nl >> 5)] * Wg[c * 32 + (nl & 31)];
    }
    __syncthreads();

    const int n0 = (tid & 63) * 4;
    const int d0 = (tid >> 6) * 16;
    unsigned long long acc[8][4];
    #pragma unroll
    for (int i = 0; i < 8; i++)
        #pragma unroll
        for (int j = 0; j < 4; j++) acc[i][j] = 0ull;

    {
        const float* up = s_u + n0;
        const float* wp = s_w1t + d0;
        #pragma unroll 2
        for (int c = 0; c < 64; c++) {
            float4 u4 = *(const float4*)(up + c * 256);
            unsigned long long ud0 = pack2(u4.x, u4.x);
            unsigned long long ud1 = pack2(u4.y, u4.y);
            unsigned long long ud2 = pack2(u4.z, u4.z);
            unsigned long long ud3 = pack2(u4.w, u4.w);
            const ulonglong2* wr = (const ulonglong2*)(wp + c * 64);
            #pragma unroll
            for (int i = 0; i < 4; i++) {
                ulonglong2 wv = wr[i];
                acc[2 * i][0] = ffma2(wv.x, ud0, acc[2 * i][0]);
                acc[2 * i][1] = ffma2(wv.x, ud1, acc[2 * i][1]);
                acc[2 * i][2] = ffma2(wv.x, ud2, acc[2 * i][2]);
                acc[2 * i][3] = ffma2(wv.x, ud3, acc[2 * i][3]);
                acc[2 * i + 1][0] = ffma2(wv.y, ud0, acc[2 * i + 1][0]);
                acc[2 * i + 1][1] = ffma2(wv.y, ud1, acc[2 * i + 1][1]);
                acc[2 * i + 1][2] = ffma2(wv.y, ud2, acc[2 * i + 1][2]);
                acc[2 * i + 1][3] = ffma2(wv.y, ud3, acc[2 * i + 1][3]);
            }
        }
    }
    __syncthreads();

    #pragma unroll
    for (int i = 0; i < 8; i++) {
        int d = d0 + 2 * i;
        float blo = s_B[d], bhi = s_B[d + 1];
        #pragma unroll
        for (int j = 0; j < 4; j++) {
            float lo, hi;
            unpack2(acc[i][j], lo, hi);
            s_u[d * 256 + n0 + j] = fmaxf(lo + blo, 0.f);
            s_u[(d + 1) * 256 + n0 + j] = fmaxf(hi + bhi, 0.f);
        }
    }
    __syncthreads();

    const int e0 = (tid >> 6) * 8;
    unsigned long long acc2[8][2];
    #pragma unroll
    for (int i = 0; i < 8; i++) { acc2[i][0] = 0ull; acc2[i][1] = 0ull; }
    {
        const float* dp = s_u + n0;
        const unsigned long long* wp2 = s_w2d + e0;
        #pragma unroll 2
        for (int d = 0; d < 64; d++) {
            ulonglong2 uu = *(const ulonglong2*)(dp + d * 256);
            const ulonglong2* wd = (const ulonglong2*)(wp2 + d * 32);
            #pragma unroll
            for (int i = 0; i < 4; i++) {
                ulonglong2 wv = wd[i];
                acc2[2 * i][0] = ffma2(wv.x, uu.x, acc2[2 * i][0]);
                acc2[2 * i][1] = ffma2(wv.x, uu.y, acc2[2 * i][1]);
                acc2[2 * i + 1][0] = ffma2(wv.y, uu.x, acc2[2 * i + 1][0]);
                acc2[2 * i + 1][1] = ffma2(wv.y, uu.y, acc2[2 * i + 1][1]);
            }
        }
    }

    const int xy = pos0 + (n0 >> 5);
    const int g0 = n0 & 31;
    #pragma unroll
    for (int e = 0; e < 8; e++) {
        float v0, v1, v2, v3;
        unpack2(acc2[e][0], v0, v1);
        unpack2(acc2[e][1], v2, v3);
        float bb = s_b2[e0 + e];
        float4 vv = make_float4(v0 + bb, v1 + bb, v2 + bb, v3 + bb);
        *(float4*)&out[(((size_t)b * 32 + e0 + e) * 1024 + xy) * 32 + g0] = vv;
    }
}

// ---------------- ft_g: per (b,e) max over contiguous 32768 values ---------------
__global__ void k_ftg(const float* __restrict__ outv, float* __restrict__ tail) {
    int bc = blockIdx.x;                   // 256
    int tid = threadIdx.x;                 // 256
    const float4* p = (const float4*)(outv + (size_t)bc * 32768);
    float m = -3.4e38f;
    for (int i = tid; i < 8192; i += 256) {
        float4 v = p[i];
        m = fmaxf(m, fmaxf(fmaxf(v.x, v.y), fmaxf(v.z, v.w)));
    }
    __shared__ float red[8];
    for (int o = 16; o > 0; o >>= 1) m = fmaxf(m, __shfl_xor_sync(0xffffffffu, m, o));
    if ((tid & 31) == 0) red[tid >> 5] = m;
    __syncthreads();
    if (tid == 0) {
        for (int i = 1; i < 8; i++) m = fmaxf(m, red[i]);
        tail[bc] = m;
    }
}

// ---------------- launch --------------------------------------------------------
#define SMEM_C1 ((8 * 4 * 40 + 72 * 32) * 4)
#define SMEM_C2 ((32 * 6 * 40 + 288 * 32) * 4)

extern "C" void kernel_launch(void* const* d_in, const int* in_sizes, int n_in,
                              void* d_out, int out_size) {
    const float* pts   = (const float*)d_in[0];
    const float* scale = (const float*)d_in[1];
    const float* sigma = (const float*)d_in[2];
    const float* A     = (const float*)d_in[3];
    const float* icmp  = (const float*)d_in[4];
    int base = (n_in >= 16) ? 7 : 5;     // skip res_pt/res_r int scalars if present
    const float* Ws1 = (const float*)d_in[base + 0];
    const float* bs1 = (const float*)d_in[base + 1];
    const float* Ws2 = (const float*)d_in[base + 2];
    const float* bs2 = (const float*)d_in[base + 3];
    const float* Wg  = (const float*)d_in[base + 4];
    const float* W1  = (const float*)d_in[base + 5];
    const float* b1  = (const float*)d_in[base + 6];
    const float* W2  = (const float*)d_in[base + 7];
    const float* b2  = (const float*)d_in[base + 8];
    float* out = (float*)d_out;

    float *ftp = nullptr, *h1p = nullptr, *h2p = nullptr, *wc1p = nullptr, *wc2p = nullptr;
    cudaGetSymbolAddress((void**)&ftp, g_ft);
    cudaGetSymbolAddress((void**)&h1p, g_h1);
    cudaGetSymbolAddress((void**)&h2p, g_h2);
    cudaGetSymbolAddress((void**)&wc1p, g_wc1);
    cudaGetSymbolAddress((void**)&wc2p, g_wc2);

    static int attr_done = 0;
    if (!attr_done) {
        cudaFuncSetAttribute(k_main, cudaFuncAttributeMaxDynamicSharedMemorySize, SMEM_MAIN);
        cudaFuncSetAttribute(k_cgemm<32, 64, 32, 4, 32>,
                             cudaFuncAttributeMaxDynamicSharedMemorySize, SMEM_C2);
        attr_done = 1;
    }

    k_init<<<256, 256>>>(Ws1, Ws2, W1, W2);
    k_scatter<<<(NB * NPT + 255) / 256, 256>>>(pts, scale, sigma, A, icmp);
    // conv1: 8->32, ROWS=2, 128 threads, grid (16,1,8) = 128 blocks
    k_cgemm<8, 32, 32, 2, 16><<<dim3(16, 1, 8), 128, SMEM_C1>>>(ftp, wc1p, bs1, h1p);
    // conv2: 32->64, ROWS=4, 256 threads, OCB=32, grid (8,2,8) = 128 blocks
    k_cgemm<32, 64, 32, 4, 32><<<dim3(8, 2, 8), 256, SMEM_C2>>>(h1p, wc2p, bs2, h2p);
    k_ftmax<<<512, 256>>>(Wg);
    k_bvec<<<1, 512>>>(W1, b1);
    k_main<<<dim3(128, NB), 256, SMEM_MAIN>>>(Wg, b2, out);
    k_ftg<<<256, 256>>>(out, out + (size_t)NB * 32 * 1024 * 32);
}